// round 1
// baseline (speedup 1.0000x reference)
#include <cuda_runtime.h>
#include <cuda_bf16.h>
#include <math_constants.h>

// Problem constants
#define Bq 8
#define Nq 2048
#define Dq 512
#define Hq 512
#define ROWS (Bq * Nq)          // 16384

// GEMM tiling
#define BM 128
#define BN 128
#define BK 16
#define TM 8
#define TN 8

// Scratch (device globals; no allocation allowed)
__device__ float g_q[ROWS * Hq];
__device__ float g_k[ROWS * Hq];
__device__ float g_v[ROWS * Hq];
__device__ float g_attn[(long long)Bq * Nq * Nq];   // 134 MB
__device__ float g_tmp[ROWS * Dq];

// C[M,N] = alpha * A[M,K] @ (TRANSB ? B[N,K]^T : B[K,N]) (+ bias[col]) (+ res)
// lda = K, ldb = TRANSB ? K : N, ldc = N. Batched via blockIdx.z strides.
template<bool TRANSB, bool BIAS, bool RES>
__global__ __launch_bounds__(256) void gemm_k(
    const float* __restrict__ A, const float* __restrict__ B,
    const float* __restrict__ bias, const float* __restrict__ res,
    float* __restrict__ C,
    int M, int N, int K,
    long long sA, long long sB, long long sC,
    float alpha)
{
    const int bz = blockIdx.z;
    A += (long long)bz * sA;
    B += (long long)bz * sB;
    C += (long long)bz * sC;
    const float* Rp = RES ? (res + (long long)bz * sC) : nullptr;

    __shared__ float As[BK][BM];
    __shared__ float Bs[BK][BN];

    const int tid = threadIdx.x;
    const int row0 = blockIdx.y * BM;
    const int col0 = blockIdx.x * BN;

    float acc[TM][TN];
#pragma unroll
    for (int m = 0; m < TM; m++)
#pragma unroll
        for (int n = 0; n < TN; n++) acc[m][n] = 0.f;

    const int ty = tid >> 4;       // 0..15
    const int tx = tid & 15;       // 0..15

    for (int k0 = 0; k0 < K; k0 += BK) {
        // ---- load A tile (transpose into As[k][m]) : 2 x float4 per thread
#pragma unroll
        for (int i = 0; i < 2; i++) {
            int idx = tid + i * 256;          // 0..511
            int r  = idx >> 2;                // 0..127
            int kc = (idx & 3) * 4;           // 0,4,8,12
            float4 va = *(const float4*)(A + (long long)(row0 + r) * K + k0 + kc);
            As[kc + 0][r] = va.x;
            As[kc + 1][r] = va.y;
            As[kc + 2][r] = va.z;
            As[kc + 3][r] = va.w;
        }
        // ---- load B tile
        if (TRANSB) {
#pragma unroll
            for (int i = 0; i < 2; i++) {
                int idx = tid + i * 256;
                int r  = idx >> 2;            // 0..127 (output col)
                int kc = (idx & 3) * 4;
                float4 vb = *(const float4*)(B + (long long)(col0 + r) * K + k0 + kc);
                Bs[kc + 0][r] = vb.x;
                Bs[kc + 1][r] = vb.y;
                Bs[kc + 2][r] = vb.z;
                Bs[kc + 3][r] = vb.w;
            }
        } else {
#pragma unroll
            for (int i = 0; i < 2; i++) {
                int idx = tid + i * 256;
                int kk = idx >> 5;            // 0..15
                int nc = (idx & 31) * 4;      // 0..124
                *(float4*)&Bs[kk][nc] =
                    *(const float4*)(B + (long long)(k0 + kk) * N + col0 + nc);
            }
        }
        __syncthreads();

        // ---- compute
#pragma unroll
        for (int kk = 0; kk < BK; kk++) {
            float a[TM], b[TN];
#pragma unroll
            for (int m = 0; m < TM; m++) a[m] = As[kk][ty * TM + m];
#pragma unroll
            for (int n = 0; n < TN; n++) b[n] = Bs[kk][tx * TN + n];
#pragma unroll
            for (int m = 0; m < TM; m++)
#pragma unroll
                for (int n = 0; n < TN; n++) acc[m][n] = fmaf(a[m], b[n], acc[m][n]);
        }
        __syncthreads();
    }

    // ---- epilogue
#pragma unroll
    for (int m = 0; m < TM; m++) {
        int r = row0 + ty * TM + m;
#pragma unroll
        for (int n = 0; n < TN; n += 4) {
            int c = col0 + tx * TN + n;
            float4 v;
            v.x = acc[m][n + 0] * alpha;
            v.y = acc[m][n + 1] * alpha;
            v.z = acc[m][n + 2] * alpha;
            v.w = acc[m][n + 3] * alpha;
            if (BIAS) {
                v.x += bias[c + 0]; v.y += bias[c + 1];
                v.z += bias[c + 2]; v.w += bias[c + 3];
            }
            if (RES) {
                float4 rr = *(const float4*)(Rp + (long long)r * N + c);
                v.x += rr.x; v.y += rr.y; v.z += rr.z; v.w += rr.w;
            }
            *(float4*)(C + (long long)r * N + c) = v;
        }
    }
}

// Row softmax over S[16384][2048], in place.
__global__ __launch_bounds__(256) void softmax_k(float* __restrict__ S)
{
    __shared__ float red[256];
    const long long row = blockIdx.x;
    float* p = S + row * (long long)Nq;
    const int t = threadIdx.x;

    float v[8];
    float mx = -CUDART_INF_F;
#pragma unroll
    for (int i = 0; i < 8; i++) {
        v[i] = p[t + i * 256];
        mx = fmaxf(mx, v[i]);
    }
    red[t] = mx;
    __syncthreads();
    for (int s = 128; s > 0; s >>= 1) {
        if (t < s) red[t] = fmaxf(red[t], red[t + s]);
        __syncthreads();
    }
    const float m = red[0];
    __syncthreads();

    float sum = 0.f;
#pragma unroll
    for (int i = 0; i < 8; i++) {
        v[i] = __expf(v[i] - m);
        sum += v[i];
    }
    red[t] = sum;
    __syncthreads();
    for (int s = 128; s > 0; s >>= 1) {
        if (t < s) red[t] += red[t + s];
        __syncthreads();
    }
    const float inv = 1.f / red[0];
#pragma unroll
    for (int i = 0; i < 8; i++) p[t + i * 256] = v[i] * inv;
}

// LayerNorm over last dim (512) of in[16384][512] -> out
__global__ __launch_bounds__(256) void ln_k(
    const float* __restrict__ in, const float* __restrict__ gamma,
    const float* __restrict__ beta, float* __restrict__ out)
{
    __shared__ float red[256];
    const long long row = blockIdx.x;
    const float* p = in + row * (long long)Dq;
    const int t = threadIdx.x;

    float a = p[t], b = p[t + 256];

    red[t] = a + b;
    __syncthreads();
    for (int s = 128; s > 0; s >>= 1) {
        if (t < s) red[t] += red[t + s];
        __syncthreads();
    }
    const float mu = red[0] * (1.f / Dq);
    __syncthreads();

    float da = a - mu, db = b - mu;
    red[t] = da * da + db * db;
    __syncthreads();
    for (int s = 128; s > 0; s >>= 1) {
        if (t < s) red[t] += red[t + s];
        __syncthreads();
    }
    const float inv = rsqrtf(red[0] * (1.f / Dq) + 1e-5f);

    out[row * Dq + t]       = da * inv * gamma[t]       + beta[t];
    out[row * Dq + t + 256] = db * inv * gamma[t + 256] + beta[t + 256];
}

extern "C" void kernel_launch(void* const* d_in, const int* in_sizes, int n_in,
                              void* d_out, int out_size)
{
    const float* X   = (const float*)d_in[0];
    const float* Wq  = (const float*)d_in[1];
    const float* bq  = (const float*)d_in[2];
    const float* Wk  = (const float*)d_in[3];
    const float* bk  = (const float*)d_in[4];
    const float* Wv  = (const float*)d_in[5];
    const float* bv  = (const float*)d_in[6];
    const float* Wo  = (const float*)d_in[7];
    const float* bo  = (const float*)d_in[8];
    const float* ga  = (const float*)d_in[9];
    const float* be  = (const float*)d_in[10];
    float* out = (float*)d_out;

    void *pq, *pk, *pv, *pattn, *ptmp;
    cudaGetSymbolAddress(&pq, g_q);
    cudaGetSymbolAddress(&pk, g_k);
    cudaGetSymbolAddress(&pv, g_v);
    cudaGetSymbolAddress(&pattn, g_attn);
    cudaGetSymbolAddress(&ptmp, g_tmp);
    float* q    = (float*)pq;
    float* k    = (float*)pk;
    float* v    = (float*)pv;
    float* attn = (float*)pattn;
    float* tmp  = (float*)ptmp;

    const float inv_sqrt_h = 0.04419417382415922f;  // 1/sqrt(512)

    dim3 blk(256);

    // QKV projections: [16384,512] @ [512,512] + bias
    {
        dim3 grd(Hq / BN, ROWS / BM, 1);
        gemm_k<false, true, false><<<grd, blk>>>(X, Wq, bq, nullptr, q,
                                                 ROWS, Hq, Dq, 0, 0, 0, 1.f);
        gemm_k<false, true, false><<<grd, blk>>>(X, Wk, bk, nullptr, k,
                                                 ROWS, Hq, Dq, 0, 0, 0, 1.f);
        gemm_k<false, true, false><<<grd, blk>>>(X, Wv, bv, nullptr, v,
                                                 ROWS, Hq, Dq, 0, 0, 0, 1.f);
    }

    // scores = q @ k^T / sqrt(H), batched over B
    {
        dim3 grd(Nq / BN, Nq / BM, Bq);
        gemm_k<true, false, false><<<grd, blk>>>(q, k, nullptr, nullptr, attn,
                                                 Nq, Nq, Hq,
                                                 (long long)Nq * Hq, (long long)Nq * Hq,
                                                 (long long)Nq * Nq, inv_sqrt_h);
    }

    // softmax rows
    softmax_k<<<ROWS, blk>>>(attn);

    // ctx = attn @ v  (reuse q as ctx buffer)
    {
        dim3 grd(Hq / BN, Nq / BM, Bq);
        gemm_k<false, false, false><<<grd, blk>>>(attn, v, nullptr, nullptr, q,
                                                  Nq, Hq, Nq,
                                                  (long long)Nq * Nq, (long long)Nq * Hq,
                                                  (long long)Nq * Hq, 1.f);
    }

    // out = ctx @ Wo + bo + X
    {
        dim3 grd(Dq / BN, ROWS / BM, 1);
        gemm_k<false, true, true><<<grd, blk>>>(q, Wo, bo, X, tmp,
                                                ROWS, Dq, Hq, 0, 0, 0, 1.f);
    }

    // LayerNorm
    ln_k<<<ROWS, blk>>>(tmp, ga, be, out);
}

// round 3
// speedup vs baseline: 3.3478x; 3.3478x over previous
#include <cuda_runtime.h>
#include <cstdint>
#include <math_constants.h>

// ---------------- problem constants ----------------
#define Bq 8
#define Nq 2048
#define Dq 512
#define Hq 512
#define ROWS (Bq * Nq)          // 16384

// ---------------- scratch (device globals) ----------------
__device__ float g_q[(size_t)ROWS * Hq];                 // q, later reused for pre-LN out
__device__ float g_k[(size_t)ROWS * Hq];                 // k, later reused for ctx
__device__ float g_vT[(size_t)Hq * ROWS];                // v transposed [H, B*N]
__device__ float g_attn[(size_t)Bq * Nq * Nq];           // 134 MB
__device__ float g_wt[(size_t)4 * Dq * Hq];              // WqT, WkT, WvT, WoT

// ---------------- helpers ----------------
__device__ __forceinline__ uint32_t smem_u32(const void* p) {
    uint32_t a;
    asm("{ .reg .u64 t; cvta.to.shared.u64 t, %1; cvt.u32.u64 %0, t; }" : "=r"(a) : "l"(p));
    return a;
}
__device__ __forceinline__ uint32_t f2tf32(float f) {
    uint32_t r;
    asm("cvt.rna.tf32.f32 %0, %1;" : "=r"(r) : "f"(f));
    return r;
}
#define LDSM_X4(r0, r1, r2, r3, addr) \
    asm volatile("ldmatrix.sync.aligned.m8n8.x4.shared.b16 {%0,%1,%2,%3}, [%4];" \
        : "=r"(r0), "=r"(r1), "=r"(r2), "=r"(r3) : "r"(addr))

__device__ __forceinline__ void mma_tf32(float* d, const uint32_t* a, const uint32_t* b) {
    asm volatile(
        "mma.sync.aligned.m16n8k8.row.col.f32.tf32.tf32.f32 "
        "{%0,%1,%2,%3}, {%4,%5,%6,%7}, {%8,%9}, {%0,%1,%2,%3};"
        : "+f"(d[0]), "+f"(d[1]), "+f"(d[2]), "+f"(d[3])
        : "r"(a[0]), "r"(a[1]), "r"(a[2]), "r"(a[3]), "r"(b[0]), "r"(b[1]));
}

// ---------------- tf32 mma.sync GEMM ----------------
// C[M,N] = alpha * A[M,K] @ B[N,K]^T (+ bias) (+ res). A,B K-major.
// BIASMODE: 0 none, 1 bias[col], 2 bias[row].
// Tile 128x128x32; 256 threads; 8 warps (2 M x 4 N), warp tile 64x32.
// SMEM rows padded to 36 floats (144 B): conflict-free STS.128 and ldmatrix.
#define ROWPAD 36
#define STAGE_BYTES (128 * ROWPAD * 4)          // 18432
#define SMEM_TOTAL (4 * STAGE_BYTES)            // A0,A1,B0,B1 = 73728

template<int BIASMODE, bool RES>
__global__ __launch_bounds__(256) void mma_gemm(
    const float* __restrict__ A, const float* __restrict__ B,
    const float* __restrict__ bias, const float* __restrict__ resid,
    float* __restrict__ C,
    int K, int lda, int ldb, int ldc,
    long long sA, long long sB, long long sC, float alpha)
{
    extern __shared__ char smem[];
    const uint32_t sb = smem_u32(smem);
    const int tid = threadIdx.x;
    const int wid = tid >> 5;
    const int l   = tid & 31;
    const int wm  = wid & 1;          // 2 warp rows (M)
    const int wn  = wid >> 1;         // 4 warp cols (N)
    const int bz  = blockIdx.z;
    const int row0 = blockIdx.y * 128;
    const int col0 = blockIdx.x * 128;

    A += (long long)bz * sA + (long long)row0 * lda;
    B += (long long)bz * sB + (long long)col0 * ldb;
    float* Cp = C + (long long)bz * sC + (long long)row0 * ldc + col0;
    const float* Rp = RES ? (resid + (long long)bz * sC + (long long)row0 * ldc + col0)
                          : nullptr;

    // ---- loader mapping: thread handles 4 float4 chunks per tile
    const int r0 = tid >> 3;          // 0..31, +32 per chunk
    const int q  = tid & 7;           // float4 column within 32-float row
    const float* Ag = A + (long long)r0 * lda + q * 4;
    const float* Bg = B + (long long)r0 * ldb + q * 4;
    char* sA0 = smem + (size_t)(r0 * ROWPAD + q * 4) * 4;         // + i*32*144 + buf*STAGE
    char* sB0 = smem + 2 * STAGE_BYTES + (size_t)(r0 * ROWPAD + q * 4) * 4;

    // ---- fragment smem addresses (per lane)
    const uint32_t a_off = sb
        + (uint32_t)(((wm * 64 + (l & 15)) * ROWPAD + ((l >> 4) & 1) * 4) * 4);
    const uint32_t b_off = sb + 2 * STAGE_BYTES
        + (uint32_t)(((wn * 32 + (l & 7) + ((l >> 4) & 1) * 8) * ROWPAD
                      + ((l >> 3) & 1) * 4) * 4);

    float acc[4][4][4];
#pragma unroll
    for (int mt = 0; mt < 4; mt++)
#pragma unroll
        for (int nt = 0; nt < 4; nt++)
#pragma unroll
            for (int i = 0; i < 4; i++) acc[mt][nt][i] = 0.f;

    float4 ra[4], rb[4];

    auto ldg_stage = [&](int s) {
        const float* ap = Ag + s * 32;
        const float* bp = Bg + s * 32;
#pragma unroll
        for (int i = 0; i < 4; i++) {
            ra[i] = *(const float4*)(ap + (long long)(32 * i) * lda);
            rb[i] = *(const float4*)(bp + (long long)(32 * i) * ldb);
        }
    };
    auto sts_stage = [&](int buf) {
        char* da = sA0 + buf * STAGE_BYTES;
        char* db = sB0 + buf * STAGE_BYTES;
#pragma unroll
        for (int i = 0; i < 4; i++) {
            uint4 ta, tb;
            ta.x = f2tf32(ra[i].x); ta.y = f2tf32(ra[i].y);
            ta.z = f2tf32(ra[i].z); ta.w = f2tf32(ra[i].w);
            tb.x = f2tf32(rb[i].x); tb.y = f2tf32(rb[i].y);
            tb.z = f2tf32(rb[i].z); tb.w = f2tf32(rb[i].w);
            *(uint4*)(da + (size_t)i * 32 * ROWPAD * 4) = ta;
            *(uint4*)(db + (size_t)i * 32 * ROWPAD * 4) = tb;
        }
    };
    auto compute_stage = [&](int buf) {
        const uint32_t ab = a_off + buf * STAGE_BYTES;
        const uint32_t bb = b_off + buf * STAGE_BYTES;
#pragma unroll
        for (int kb = 0; kb < 4; kb++) {
            uint32_t afr[4][4], bfr[2][4];
#pragma unroll
            for (int mt = 0; mt < 4; mt++)
                LDSM_X4(afr[mt][0], afr[mt][1], afr[mt][2], afr[mt][3],
                        ab + mt * (16 * ROWPAD * 4) + kb * 32);
#pragma unroll
            for (int t = 0; t < 2; t++)
                LDSM_X4(bfr[t][0], bfr[t][1], bfr[t][2], bfr[t][3],
                        bb + t * (16 * ROWPAD * 4) + kb * 32);
#pragma unroll
            for (int mt = 0; mt < 4; mt++)
#pragma unroll
                for (int nt = 0; nt < 4; nt++)
                    mma_tf32(acc[mt][nt], afr[mt], &bfr[nt >> 1][2 * (nt & 1)]);
        }
    };

    const int nst = K >> 5;
    ldg_stage(0);
    sts_stage(0);
    __syncthreads();
    for (int s = 0; s < nst; s++) {
        if (s + 1 < nst) ldg_stage(s + 1);
        compute_stage(s & 1);
        if (s + 1 < nst) sts_stage((s + 1) & 1);
        __syncthreads();
    }

    // ---- epilogue (register fragments -> global)
    const int lr  = l >> 2;          // 0..7
    const int lc2 = (l & 3) * 2;
#pragma unroll
    for (int mt = 0; mt < 4; mt++) {
        const int rA = wm * 64 + mt * 16 + lr;
        float blo = 0.f, bhi = 0.f;
        if (BIASMODE == 2) { blo = bias[row0 + rA]; bhi = bias[row0 + rA + 8]; }
#pragma unroll
        for (int nt = 0; nt < 4; nt++) {
            const int cA = wn * 32 + nt * 8 + lc2;
            float2 v0, v1;
            v0.x = acc[mt][nt][0] * alpha; v0.y = acc[mt][nt][1] * alpha;
            v1.x = acc[mt][nt][2] * alpha; v1.y = acc[mt][nt][3] * alpha;
            if (BIASMODE == 1) {
                float2 bb2 = *(const float2*)(bias + col0 + cA);
                v0.x += bb2.x; v0.y += bb2.y; v1.x += bb2.x; v1.y += bb2.y;
            } else if (BIASMODE == 2) {
                v0.x += blo; v0.y += blo; v1.x += bhi; v1.y += bhi;
            }
            if (RES) {
                float2 q0 = *(const float2*)(Rp + (long long)rA * ldc + cA);
                float2 q1 = *(const float2*)(Rp + (long long)(rA + 8) * ldc + cA);
                v0.x += q0.x; v0.y += q0.y; v1.x += q1.x; v1.y += q1.y;
            }
            *(float2*)(Cp + (long long)rA * ldc + cA) = v0;
            *(float2*)(Cp + (long long)(rA + 8) * ldc + cA) = v1;
        }
    }
}

// ---------------- weight transpose: WT[n,k] = W[k,n], 4 x 512x512 ----------------
__global__ __launch_bounds__(256) void transpose4_k(
    const float* __restrict__ w0, const float* __restrict__ w1,
    const float* __restrict__ w2, const float* __restrict__ w3,
    float* __restrict__ out)
{
    __shared__ float t[32][33];
    const int z = blockIdx.z;
    const float* W = (z == 0) ? w0 : (z == 1) ? w1 : (z == 2) ? w2 : w3;
    float* O = out + (size_t)z * Dq * Hq;
    const int tx = threadIdx.x & 31;
    const int ty = threadIdx.x >> 5;
    const int x = blockIdx.x * 32 + tx;
    const int y0 = blockIdx.y * 32;
#pragma unroll
    for (int i = ty; i < 32; i += 8) t[i][tx] = W[(y0 + i) * Hq + x];
    __syncthreads();
    const int ox = blockIdx.y * 32 + tx;
#pragma unroll
    for (int i = ty; i < 32; i += 8) O[(blockIdx.x * 32 + i) * Dq + ox] = t[tx][i];
}

// ---------------- softmax over rows of [16384][2048] ----------------
__global__ __launch_bounds__(256) void softmax_k(float* __restrict__ S)
{
    __shared__ float red[256];
    float* p = S + blockIdx.x * (long long)Nq;
    const int t = threadIdx.x;
    float v[8];
    float mx = -CUDART_INF_F;
#pragma unroll
    for (int i = 0; i < 8; i++) { v[i] = p[t + i * 256]; mx = fmaxf(mx, v[i]); }
    red[t] = mx; __syncthreads();
    for (int s = 128; s > 0; s >>= 1) { if (t < s) red[t] = fmaxf(red[t], red[t + s]); __syncthreads(); }
    const float m = red[0]; __syncthreads();
    float sum = 0.f;
#pragma unroll
    for (int i = 0; i < 8; i++) { v[i] = __expf(v[i] - m); sum += v[i]; }
    red[t] = sum; __syncthreads();
    for (int s = 128; s > 0; s >>= 1) { if (t < s) red[t] += red[t + s]; __syncthreads(); }
    const float inv = 1.f / red[0];
#pragma unroll
    for (int i = 0; i < 8; i++) p[t + i * 256] = v[i] * inv;
}

// ---------------- LayerNorm over last dim (512) ----------------
__global__ __launch_bounds__(256) void ln_k(
    const float* __restrict__ in, const float* __restrict__ gamma,
    const float* __restrict__ beta, float* __restrict__ out)
{
    __shared__ float red[256];
    const float* p = in + blockIdx.x * (long long)Dq;
    const int t = threadIdx.x;
    float a = p[t], b = p[t + 256];
    red[t] = a + b; __syncthreads();
    for (int s = 128; s > 0; s >>= 1) { if (t < s) red[t] += red[t + s]; __syncthreads(); }
    const float mu = red[0] * (1.f / Dq); __syncthreads();
    float da = a - mu, db = b - mu;
    red[t] = da * da + db * db; __syncthreads();
    for (int s = 128; s > 0; s >>= 1) { if (t < s) red[t] += red[t + s]; __syncthreads(); }
    const float inv = rsqrtf(red[0] * (1.f / Dq) + 1e-5f);
    out[blockIdx.x * (long long)Dq + t]       = da * inv * gamma[t]       + beta[t];
    out[blockIdx.x * (long long)Dq + t + 256] = db * inv * gamma[t + 256] + beta[t + 256];
}

// ---------------- launch ----------------
extern "C" void kernel_launch(void* const* d_in, const int* in_sizes, int n_in,
                              void* d_out, int out_size)
{
    const float* X   = (const float*)d_in[0];
    const float* Wq  = (const float*)d_in[1];
    const float* bqp = (const float*)d_in[2];
    const float* Wk  = (const float*)d_in[3];
    const float* bkp = (const float*)d_in[4];
    const float* Wv  = (const float*)d_in[5];
    const float* bvp = (const float*)d_in[6];
    const float* Wo  = (const float*)d_in[7];
    const float* bop = (const float*)d_in[8];
    const float* ga  = (const float*)d_in[9];
    const float* be  = (const float*)d_in[10];
    float* out = (float*)d_out;

    void *pq, *pk, *pvT, *pattn, *pwt;
    cudaGetSymbolAddress(&pq, g_q);
    cudaGetSymbolAddress(&pk, g_k);
    cudaGetSymbolAddress(&pvT, g_vT);
    cudaGetSymbolAddress(&pattn, g_attn);
    cudaGetSymbolAddress(&pwt, g_wt);
    float* q    = (float*)pq;
    float* k    = (float*)pk;
    float* vT   = (float*)pvT;
    float* attn = (float*)pattn;
    float* wt   = (float*)pwt;
    float* WqT = wt;
    float* WkT = wt + (size_t)Dq * Hq;
    float* WvT = wt + (size_t)2 * Dq * Hq;
    float* WoT = wt + (size_t)3 * Dq * Hq;

    cudaFuncSetAttribute(mma_gemm<0, false>, cudaFuncAttributeMaxDynamicSharedMemorySize, SMEM_TOTAL);
    cudaFuncSetAttribute(mma_gemm<1, false>, cudaFuncAttributeMaxDynamicSharedMemorySize, SMEM_TOTAL);
    cudaFuncSetAttribute(mma_gemm<2, false>, cudaFuncAttributeMaxDynamicSharedMemorySize, SMEM_TOTAL);
    cudaFuncSetAttribute(mma_gemm<1, true>,  cudaFuncAttributeMaxDynamicSharedMemorySize, SMEM_TOTAL);

    const float inv_sqrt_h = 0.04419417382415922f;  // 1/sqrt(512)
    dim3 blk(256);

    // 0. transpose weights -> K-major [N,K]
    transpose4_k<<<dim3(16, 16, 4), blk>>>(Wq, Wk, Wv, Wo, wt);

    // 1. q = X @ Wq + bq
    mma_gemm<1, false><<<dim3(Hq / 128, ROWS / 128, 1), blk, SMEM_TOTAL>>>(
        X, WqT, bqp, nullptr, q, Dq, Dq, Dq, Hq, 0, 0, 0, 1.f);
    // 2. k = X @ Wk + bk
    mma_gemm<1, false><<<dim3(Hq / 128, ROWS / 128, 1), blk, SMEM_TOTAL>>>(
        X, WkT, bkp, nullptr, k, Dq, Dq, Dq, Hq, 0, 0, 0, 1.f);
    // 3. vT[h, n] = Wv[:,h] . X[n,:] + bv[h]   (A=WvT, B=X)
    mma_gemm<2, false><<<dim3(ROWS / 128, Hq / 128, 1), blk, SMEM_TOTAL>>>(
        WvT, X, bvp, nullptr, vT, Dq, Dq, Dq, ROWS, 0, 0, 0, 1.f);
    // 4. scores = q @ k^T / sqrt(H), batched
    mma_gemm<0, false><<<dim3(Nq / 128, Nq / 128, Bq), blk, SMEM_TOTAL>>>(
        q, k, nullptr, nullptr, attn, Hq, Hq, Hq, Nq,
        (long long)Nq * Hq, (long long)Nq * Hq, (long long)Nq * Nq, inv_sqrt_h);
    // 5. softmax
    softmax_k<<<ROWS, blk>>>(attn);
    // 6. ctx = attn @ v  (B = vT columns, ldb = ROWS) -> g_k
    mma_gemm<0, false><<<dim3(Hq / 128, Nq / 128, Bq), blk, SMEM_TOTAL>>>(
        attn, vT, nullptr, nullptr, k, Nq, Nq, ROWS, Hq,
        (long long)Nq * Nq, (long long)Nq, (long long)Nq * Hq, 1.f);
    // 7. out_pre = ctx @ Wo + bo + X -> g_q
    mma_gemm<1, true><<<dim3(Dq / 128, ROWS / 128, 1), blk, SMEM_TOTAL>>>(
        k, WoT, bop, X, q, Hq, Hq, Hq, Dq, 0, 0, 0, 1.f);
    // 8. LayerNorm
    ln_k<<<ROWS, blk>>>(q, ga, be, out);
}

// round 4
// speedup vs baseline: 5.2315x; 1.5627x over previous
#include <cuda_runtime.h>
#include <cuda_bf16.h>
#include <cstdint>
#include <math_constants.h>

// ---------------- problem constants ----------------
#define Bq 8
#define Nq 2048
#define Dq 512
#define Hq 512
#define ROWS (Bq * Nq)          // 16384

// ---------------- scratch (device globals) ----------------
__device__ __nv_bfloat16 g_xb[(size_t)ROWS * Dq];
__device__ __nv_bfloat16 g_qb[(size_t)ROWS * Hq];
__device__ __nv_bfloat16 g_kb[(size_t)ROWS * Hq];
__device__ __nv_bfloat16 g_vTb[(size_t)Hq * ROWS];
__device__ __nv_bfloat16 g_ctxb[(size_t)ROWS * Hq];
__device__ __nv_bfloat16 g_attnb[(size_t)Bq * Nq * Nq];
__device__ __nv_bfloat16 g_wtb[(size_t)4 * Dq * Hq];     // WqT, WkT, WvT, WoT (bf16)
__device__ float g_attn[(size_t)Bq * Nq * Nq];           // fp32 scores, 134 MB
__device__ float g_tmp[(size_t)ROWS * Dq];               // pre-LN

// ---------------- helpers ----------------
__device__ __forceinline__ uint32_t smem_u32(const void* p) {
    uint32_t a;
    asm("{ .reg .u64 t; cvta.to.shared.u64 t, %1; cvt.u32.u64 %0, t; }" : "=r"(a) : "l"(p));
    return a;
}
#define LDSM_X4(r0, r1, r2, r3, addr) \
    asm volatile("ldmatrix.sync.aligned.m8n8.x4.shared.b16 {%0,%1,%2,%3}, [%4];" \
        : "=r"(r0), "=r"(r1), "=r"(r2), "=r"(r3) : "r"(addr))

__device__ __forceinline__ void mma_bf16(float* d, const uint32_t* a,
                                         uint32_t b0, uint32_t b1) {
    asm volatile(
        "mma.sync.aligned.m16n8k16.row.col.f32.bf16.bf16.f32 "
        "{%0,%1,%2,%3}, {%4,%5,%6,%7}, {%8,%9}, {%0,%1,%2,%3};"
        : "+f"(d[0]), "+f"(d[1]), "+f"(d[2]), "+f"(d[3])
        : "r"(a[0]), "r"(a[1]), "r"(a[2]), "r"(a[3]), "r"(b0), "r"(b1));
}

// ---------------- bf16 mma.sync GEMM ----------------
// C[M,N] = alpha * A[M,K] @ B[N,K]^T (+ bias) (+ res). A,B bf16 K-major.
// BIASMODE: 0 none, 1 bias[col], 2 bias[row]. OUTBF16: C is bf16 else fp32.
// Tile 128x128x32; 256 threads; 8 warps (2 M x 4 N), warp tile 64x32.
// SMEM rows: 32 bf16 (64 B) padded to 80 B -> conflict-free ldmatrix.
#define RPAD_B 80
#define STAGE_B (128 * RPAD_B)                    // 10240
#define SMEM_TOTAL (4 * STAGE_B)                  // 40960 (static)

template<int BIASMODE, bool RES, bool OUTBF16>
__global__ __launch_bounds__(256) void mma_gemm(
    const __nv_bfloat16* __restrict__ A, const __nv_bfloat16* __restrict__ B,
    const float* __restrict__ bias, const float* __restrict__ resid,
    void* __restrict__ Cv,
    int K, int lda, int ldb, int ldc,
    long long sA, long long sB, long long sC, float alpha)
{
    __shared__ char smem[SMEM_TOTAL];
    const uint32_t sb = smem_u32(smem);
    const int tid = threadIdx.x;
    const int wid = tid >> 5;
    const int l   = tid & 31;
    const int wm  = wid & 1;
    const int wn  = wid >> 1;
    const int bz  = blockIdx.z;
    const int row0 = blockIdx.y * 128;
    const int col0 = blockIdx.x * 128;

    A += (long long)bz * sA + (long long)row0 * lda;
    B += (long long)bz * sB + (long long)col0 * ldb;
    const long long cbase = (long long)bz * sC + (long long)row0 * ldc + col0;
    const float* Rp = RES ? (resid + cbase) : nullptr;

    // ---- loader mapping: 2 chunks of 16B per operand per thread per stage
    const int r0 = tid >> 2;              // 0..63 (+64 for second chunk)
    const int c16 = tid & 3;              // 16B column within 64B row
    const __nv_bfloat16* Ag = A + (long long)r0 * lda + c16 * 8;
    const __nv_bfloat16* Bg = B + (long long)r0 * ldb + c16 * 8;
    char* sA0 = smem + (size_t)(r0 * RPAD_B + c16 * 16);
    char* sB0 = smem + 2 * STAGE_B + (size_t)(r0 * RPAD_B + c16 * 16);

    // ---- ldmatrix lane addresses
    const uint32_t a_off = sb
        + (uint32_t)((wm * 64 + (l & 15)) * RPAD_B + ((l >> 4) & 1) * 16);
    const uint32_t b_off = sb + 2 * STAGE_B
        + (uint32_t)((wn * 32 + (l & 15)) * RPAD_B + ((l >> 4) & 1) * 16);

    float acc[4][4][4];
#pragma unroll
    for (int mt = 0; mt < 4; mt++)
#pragma unroll
        for (int nt = 0; nt < 4; nt++)
#pragma unroll
            for (int i = 0; i < 4; i++) acc[mt][nt][i] = 0.f;

    uint4 ra[2], rb[2];
    auto ldg_stage = [&](int s) {
        const __nv_bfloat16* ap = Ag + s * 32;
        const __nv_bfloat16* bp = Bg + s * 32;
#pragma unroll
        for (int i = 0; i < 2; i++) {
            ra[i] = *(const uint4*)(ap + (long long)(64 * i) * lda);
            rb[i] = *(const uint4*)(bp + (long long)(64 * i) * ldb);
        }
    };
    auto sts_stage = [&](int buf) {
        char* da = sA0 + buf * STAGE_B;
        char* db = sB0 + buf * STAGE_B;
#pragma unroll
        for (int i = 0; i < 2; i++) {
            *(uint4*)(da + (size_t)i * 64 * RPAD_B) = ra[i];
            *(uint4*)(db + (size_t)i * 64 * RPAD_B) = rb[i];
        }
    };
    auto compute_stage = [&](int buf) {
        const uint32_t ab = a_off + buf * STAGE_B;
        const uint32_t bb = b_off + buf * STAGE_B;
#pragma unroll
        for (int kb = 0; kb < 2; kb++) {
            uint32_t afr[4][4], bfr[2][4];
#pragma unroll
            for (int mt = 0; mt < 4; mt++)
                LDSM_X4(afr[mt][0], afr[mt][1], afr[mt][2], afr[mt][3],
                        ab + mt * (16 * RPAD_B) + kb * 32);
#pragma unroll
            for (int t = 0; t < 2; t++)
                LDSM_X4(bfr[t][0], bfr[t][1], bfr[t][2], bfr[t][3],
                        bb + t * (16 * RPAD_B) + kb * 32);
#pragma unroll
            for (int mt = 0; mt < 4; mt++)
#pragma unroll
                for (int nt = 0; nt < 4; nt++)
                    mma_bf16(acc[mt][nt], afr[mt],
                             bfr[nt >> 1][nt & 1], bfr[nt >> 1][2 + (nt & 1)]);
        }
    };

    const int nst = K >> 5;
    ldg_stage(0);
    sts_stage(0);
    __syncthreads();
    for (int s = 0; s < nst; s++) {
        if (s + 1 < nst) ldg_stage(s + 1);
        compute_stage(s & 1);
        if (s + 1 < nst) sts_stage((s + 1) & 1);
        __syncthreads();
    }

    // ---- epilogue
    float* Cf = (float*)Cv;
    __nv_bfloat16* Cb = (__nv_bfloat16*)Cv;
    const int lr  = l >> 2;
    const int lc2 = (l & 3) * 2;
#pragma unroll
    for (int mt = 0; mt < 4; mt++) {
        const int rA = wm * 64 + mt * 16 + lr;
        float blo = 0.f, bhi = 0.f;
        if (BIASMODE == 2) { blo = bias[row0 + rA]; bhi = bias[row0 + rA + 8]; }
#pragma unroll
        for (int nt = 0; nt < 4; nt++) {
            const int cA = wn * 32 + nt * 8 + lc2;
            float2 v0, v1;
            v0.x = acc[mt][nt][0] * alpha; v0.y = acc[mt][nt][1] * alpha;
            v1.x = acc[mt][nt][2] * alpha; v1.y = acc[mt][nt][3] * alpha;
            if (BIASMODE == 1) {
                float2 bb2 = *(const float2*)(bias + col0 + cA);
                v0.x += bb2.x; v0.y += bb2.y; v1.x += bb2.x; v1.y += bb2.y;
            } else if (BIASMODE == 2) {
                v0.x += blo; v0.y += blo; v1.x += bhi; v1.y += bhi;
            }
            if (RES) {
                float2 q0 = *(const float2*)(Rp + (long long)rA * ldc + cA);
                float2 q1 = *(const float2*)(Rp + (long long)(rA + 8) * ldc + cA);
                v0.x += q0.x; v0.y += q0.y; v1.x += q1.x; v1.y += q1.y;
            }
            if (OUTBF16) {
                *(__nv_bfloat162*)(Cb + cbase + (long long)rA * ldc + cA) =
                    __float22bfloat162_rn(v0);
                *(__nv_bfloat162*)(Cb + cbase + (long long)(rA + 8) * ldc + cA) =
                    __float22bfloat162_rn(v1);
            } else {
                *(float2*)(Cf + cbase + (long long)rA * ldc + cA) = v0;
                *(float2*)(Cf + cbase + (long long)(rA + 8) * ldc + cA) = v1;
            }
        }
    }
}

// ---------------- X -> bf16 ----------------
__global__ __launch_bounds__(256) void cvt_x_k(const float* __restrict__ X,
                                               __nv_bfloat16* __restrict__ Xb)
{
    const size_t i = ((size_t)blockIdx.x * 256 + threadIdx.x) * 4;
    float4 v = *(const float4*)(X + i);
    __nv_bfloat162 lo = __float22bfloat162_rn(make_float2(v.x, v.y));
    __nv_bfloat162 hi = __float22bfloat162_rn(make_float2(v.z, v.w));
    *(__nv_bfloat162*)(Xb + i) = lo;
    *(__nv_bfloat162*)(Xb + i + 2) = hi;
}

// ---------------- weight transpose -> bf16: WT[n,k] = W[k,n] ----------------
__global__ __launch_bounds__(256) void transpose4_k(
    const float* __restrict__ w0, const float* __restrict__ w1,
    const float* __restrict__ w2, const float* __restrict__ w3,
    __nv_bfloat16* __restrict__ out)
{
    __shared__ float t[32][33];
    const int z = blockIdx.z;
    const float* W = (z == 0) ? w0 : (z == 1) ? w1 : (z == 2) ? w2 : w3;
    __nv_bfloat16* O = out + (size_t)z * Dq * Hq;
    const int tx = threadIdx.x & 31;
    const int ty = threadIdx.x >> 5;
    const int x = blockIdx.x * 32 + tx;
    const int y0 = blockIdx.y * 32;
#pragma unroll
    for (int i = ty; i < 32; i += 8) t[i][tx] = W[(y0 + i) * Hq + x];
    __syncthreads();
    const int ox = blockIdx.y * 32 + tx;
#pragma unroll
    for (int i = ty; i < 32; i += 8)
        O[(blockIdx.x * 32 + i) * Dq + ox] = __float2bfloat16_rn(t[tx][i]);
}

// ---------------- softmax: fp32 scores -> bf16 probs ----------------
__global__ __launch_bounds__(256) void softmax_k(const float* __restrict__ S,
                                                 __nv_bfloat16* __restrict__ P)
{
    __shared__ float red[256];
    const float* p = S + blockIdx.x * (long long)Nq;
    __nv_bfloat16* po = P + blockIdx.x * (long long)Nq;
    const int t = threadIdx.x;
    float v[8];
    float mx = -CUDART_INF_F;
#pragma unroll
    for (int i = 0; i < 8; i++) { v[i] = p[t + i * 256]; mx = fmaxf(mx, v[i]); }
    red[t] = mx; __syncthreads();
    for (int s = 128; s > 0; s >>= 1) { if (t < s) red[t] = fmaxf(red[t], red[t + s]); __syncthreads(); }
    const float m = red[0]; __syncthreads();
    float sum = 0.f;
#pragma unroll
    for (int i = 0; i < 8; i++) { v[i] = __expf(v[i] - m); sum += v[i]; }
    red[t] = sum; __syncthreads();
    for (int s = 128; s > 0; s >>= 1) { if (t < s) red[t] += red[t + s]; __syncthreads(); }
    const float inv = 1.f / red[0];
#pragma unroll
    for (int i = 0; i < 8; i++) po[t + i * 256] = __float2bfloat16_rn(v[i] * inv);
}

// ---------------- LayerNorm over last dim (512) ----------------
__global__ __launch_bounds__(256) void ln_k(
    const float* __restrict__ in, const float* __restrict__ gamma,
    const float* __restrict__ beta, float* __restrict__ out)
{
    __shared__ float red[256];
    const float* p = in + blockIdx.x * (long long)Dq;
    const int t = threadIdx.x;
    float a = p[t], b = p[t + 256];
    red[t] = a + b; __syncthreads();
    for (int s = 128; s > 0; s >>= 1) { if (t < s) red[t] += red[t + s]; __syncthreads(); }
    const float mu = red[0] * (1.f / Dq); __syncthreads();
    float da = a - mu, db = b - mu;
    red[t] = da * da + db * db; __syncthreads();
    for (int s = 128; s > 0; s >>= 1) { if (t < s) red[t] += red[t + s]; __syncthreads(); }
    const float inv = rsqrtf(red[0] * (1.f / Dq) + 1e-5f);
    out[blockIdx.x * (long long)Dq + t]       = da * inv * gamma[t]       + beta[t];
    out[blockIdx.x * (long long)Dq + t + 256] = db * inv * gamma[t + 256] + beta[t + 256];
}

// ---------------- launch ----------------
extern "C" void kernel_launch(void* const* d_in, const int* in_sizes, int n_in,
                              void* d_out, int out_size)
{
    const float* X   = (const float*)d_in[0];
    const float* Wq  = (const float*)d_in[1];
    const float* bqp = (const float*)d_in[2];
    const float* Wk  = (const float*)d_in[3];
    const float* bkp = (const float*)d_in[4];
    const float* Wv  = (const float*)d_in[5];
    const float* bvp = (const float*)d_in[6];
    const float* Wo  = (const float*)d_in[7];
    const float* bop = (const float*)d_in[8];
    const float* ga  = (const float*)d_in[9];
    const float* be  = (const float*)d_in[10];
    float* out = (float*)d_out;

    void *pxb, *pqb, *pkb, *pvTb, *pctxb, *pattnb, *pwtb, *pattn, *ptmp;
    cudaGetSymbolAddress(&pxb, g_xb);
    cudaGetSymbolAddress(&pqb, g_qb);
    cudaGetSymbolAddress(&pkb, g_kb);
    cudaGetSymbolAddress(&pvTb, g_vTb);
    cudaGetSymbolAddress(&pctxb, g_ctxb);
    cudaGetSymbolAddress(&pattnb, g_attnb);
    cudaGetSymbolAddress(&pwtb, g_wtb);
    cudaGetSymbolAddress(&pattn, g_attn);
    cudaGetSymbolAddress(&ptmp, g_tmp);
    __nv_bfloat16* xb   = (__nv_bfloat16*)pxb;
    __nv_bfloat16* qb   = (__nv_bfloat16*)pqb;
    __nv_bfloat16* kb   = (__nv_bfloat16*)pkb;
    __nv_bfloat16* vTb  = (__nv_bfloat16*)pvTb;
    __nv_bfloat16* ctxb = (__nv_bfloat16*)pctxb;
    __nv_bfloat16* attnb = (__nv_bfloat16*)pattnb;
    __nv_bfloat16* wtb  = (__nv_bfloat16*)pwtb;
    float* attn = (float*)pattn;
    float* tmp  = (float*)ptmp;
    __nv_bfloat16* WqT = wtb;
    __nv_bfloat16* WkT = wtb + (size_t)Dq * Hq;
    __nv_bfloat16* WvT = wtb + (size_t)2 * Dq * Hq;
    __nv_bfloat16* WoT = wtb + (size_t)3 * Dq * Hq;

    const float inv_sqrt_h = 0.04419417382415922f;  // 1/sqrt(512)
    dim3 blk(256);

    // 0. convert X; transpose+convert weights
    cvt_x_k<<<(ROWS * Dq) / (256 * 4), blk>>>(X, xb);
    transpose4_k<<<dim3(16, 16, 4), blk>>>(Wq, Wk, Wv, Wo, wtb);

    // 1. q = X @ Wq + bq  (bf16 out)
    mma_gemm<1, false, true><<<dim3(Hq / 128, ROWS / 128, 1), blk>>>(
        xb, WqT, bqp, nullptr, qb, Dq, Dq, Dq, Hq, 0, 0, 0, 1.f);
    // 2. k = X @ Wk + bk  (bf16 out)
    mma_gemm<1, false, true><<<dim3(Hq / 128, ROWS / 128, 1), blk>>>(
        xb, WkT, bkp, nullptr, kb, Dq, Dq, Dq, Hq, 0, 0, 0, 1.f);
    // 3. vT[h,n] = Wv[:,h].X[n,:] + bv[h]  (bf16 out, bias by row)
    mma_gemm<2, false, true><<<dim3(ROWS / 128, Hq / 128, 1), blk>>>(
        WvT, xb, bvp, nullptr, vTb, Dq, Dq, Dq, ROWS, 0, 0, 0, 1.f);
    // 4. scores = q @ k^T / sqrt(H)  (fp32 out, batched)
    mma_gemm<0, false, false><<<dim3(Nq / 128, Nq / 128, Bq), blk>>>(
        qb, kb, nullptr, nullptr, attn, Hq, Hq, Hq, Nq,
        (long long)Nq * Hq, (long long)Nq * Hq, (long long)Nq * Nq, inv_sqrt_h);
    // 5. softmax (fp32 -> bf16 probs)
    softmax_k<<<ROWS, blk>>>(attn, attnb);
    // 6. ctx = attn @ v  (bf16 out)
    mma_gemm<0, false, true><<<dim3(Hq / 128, Nq / 128, Bq), blk>>>(
        attnb, vTb, nullptr, nullptr, ctxb, Nq, Nq, ROWS, Hq,
        (long long)Nq * Nq, (long long)Nq, (long long)Nq * Hq, 1.f);
    // 7. out_pre = ctx @ Wo + bo + X  (fp32 out)
    mma_gemm<1, true, false><<<dim3(Dq / 128, ROWS / 128, 1), blk>>>(
        ctxb, WoT, bop, X, tmp, Hq, Hq, Hq, Dq, 0, 0, 0, 1.f);
    // 8. LayerNorm
    ln_k<<<ROWS, blk>>>(tmp, ga, be, out);
}

// round 5
// speedup vs baseline: 5.4401x; 1.0399x over previous
#include <cuda_runtime.h>
#include <cuda_bf16.h>
#include <cstdint>
#include <math_constants.h>

// ---------------- problem constants ----------------
#define Bq 8
#define Nq 2048
#define Dq 512
#define Hq 512
#define ROWS (Bq * Nq)          // 16384

// ---------------- scratch (device globals) ----------------
__device__ __nv_bfloat16 g_xb[(size_t)ROWS * Dq];
__device__ __nv_bfloat16 g_qb[(size_t)ROWS * Hq];
__device__ __nv_bfloat16 g_kb[(size_t)ROWS * Hq];
__device__ __nv_bfloat16 g_vTb[(size_t)Hq * ROWS];
__device__ __nv_bfloat16 g_ctxb[(size_t)ROWS * Hq];
__device__ __nv_bfloat16 g_attnb[(size_t)Bq * Nq * Nq];  // scores then probs (bf16)
__device__ __nv_bfloat16 g_wtb[(size_t)4 * Dq * Hq];     // WqT, WkT, WvT, WoT
__device__ float g_tmp[(size_t)ROWS * Dq];               // pre-LN (fp32)

// ---------------- helpers ----------------
__device__ __forceinline__ uint32_t smem_u32(const void* p) {
    uint32_t a;
    asm("{ .reg .u64 t; cvta.to.shared.u64 t, %1; cvt.u32.u64 %0, t; }" : "=r"(a) : "l"(p));
    return a;
}
#define LDSM_X4(r0, r1, r2, r3, addr) \
    asm volatile("ldmatrix.sync.aligned.m8n8.x4.shared.b16 {%0,%1,%2,%3}, [%4];" \
        : "=r"(r0), "=r"(r1), "=r"(r2), "=r"(r3) : "r"(addr))
#define CP_ASYNC16(dst, src) \
    asm volatile("cp.async.cg.shared.global [%0], [%1], 16;" :: "r"(dst), "l"(src))
#define CP_COMMIT() asm volatile("cp.async.commit_group;" ::: "memory")
#define CP_WAIT(n)  asm volatile("cp.async.wait_group %0;" :: "n"(n) : "memory")

__device__ __forceinline__ void mma_bf16(float* d, const uint32_t* a,
                                         uint32_t b0, uint32_t b1) {
    asm volatile(
        "mma.sync.aligned.m16n8k16.row.col.f32.bf16.bf16.f32 "
        "{%0,%1,%2,%3}, {%4,%5,%6,%7}, {%8,%9}, {%0,%1,%2,%3};"
        : "+f"(d[0]), "+f"(d[1]), "+f"(d[2]), "+f"(d[3])
        : "r"(a[0]), "r"(a[1]), "r"(a[2]), "r"(a[3]), "r"(b0), "r"(b1));
}

// ---------------- bf16 mma.sync GEMM, cp.async 4-stage ----------------
// C[M,N] = alpha * A[M,K] @ B[N,K]^T (+ bias) (+ res). A,B bf16 K-major.
// BIASMODE: 0 none, 1 bias[col], 2 bias[row]. OUTBF16: C bf16 else fp32.
// Tile 128x128x32; 256 threads; 8 warps (2 M x 4 N), warp tile 64x32.
// SMEM rows: 32 bf16 (64 B) padded to 80 B -> conflict-free ldmatrix.
#define RPAD_B 80
#define HALF_B (128 * RPAD_B)                     // 10240 per operand per stage
#define STAGE_T (2 * HALF_B)                      // 20480 (A + B)
#define NSTAGE 4
#define SMEM_TOTAL (NSTAGE * STAGE_T)             // 81920 (dynamic)

template<int BIASMODE, bool RES, bool OUTBF16>
__global__ __launch_bounds__(256) void mma_gemm(
    const __nv_bfloat16* __restrict__ A, const __nv_bfloat16* __restrict__ B,
    const float* __restrict__ bias, const float* __restrict__ resid,
    void* __restrict__ Cv,
    int K, int lda, int ldb, int ldc,
    long long sA, long long sB, long long sC, float alpha)
{
    extern __shared__ char smem[];
    const uint32_t sb = smem_u32(smem);
    const int tid = threadIdx.x;
    const int wid = tid >> 5;
    const int l   = tid & 31;
    const int wm  = wid & 1;
    const int wn  = wid >> 1;
    const int bz  = blockIdx.z;
    const int row0 = blockIdx.y * 128;
    const int col0 = blockIdx.x * 128;

    A += (long long)bz * sA + (long long)row0 * lda;
    B += (long long)bz * sB + (long long)col0 * ldb;
    const long long cbase = (long long)bz * sC + (long long)row0 * ldc + col0;
    const float* Rp = RES ? (resid + cbase) : nullptr;

    // ---- cp.async mapping: 4 x 16B per thread per stage (2 A, 2 B)
    const int r0  = tid >> 2;             // 0..63 (+64 second chunk)
    const int c16 = tid & 3;              // 16B column within 64B k-row
    const __nv_bfloat16* Ag = A + (long long)r0 * lda + c16 * 8;
    const __nv_bfloat16* Bg = B + (long long)r0 * ldb + c16 * 8;
    const uint32_t dstA = sb + (uint32_t)(r0 * RPAD_B + c16 * 16);
    const uint32_t dstB = dstA + HALF_B;

    // ---- ldmatrix lane addresses (within-stage offsets)
    const uint32_t a_off = sb
        + (uint32_t)((wm * 64 + (l & 15)) * RPAD_B + ((l >> 4) & 1) * 16);
    const uint32_t b_off = sb + HALF_B
        + (uint32_t)((wn * 32 + (l & 15)) * RPAD_B + ((l >> 4) & 1) * 16);

    float acc[4][4][4];
#pragma unroll
    for (int mt = 0; mt < 4; mt++)
#pragma unroll
        for (int nt = 0; nt < 4; nt++)
#pragma unroll
            for (int i = 0; i < 4; i++) acc[mt][nt][i] = 0.f;

    auto issue_stage = [&](int s) {
        const int buf = s & (NSTAGE - 1);
        const __nv_bfloat16* ap = Ag + s * 32;
        const __nv_bfloat16* bp = Bg + s * 32;
        const uint32_t da = dstA + buf * STAGE_T;
        const uint32_t db = dstB + buf * STAGE_T;
#pragma unroll
        for (int i = 0; i < 2; i++) {
            CP_ASYNC16(da + i * 64 * RPAD_B, ap + (long long)(64 * i) * lda);
            CP_ASYNC16(db + i * 64 * RPAD_B, bp + (long long)(64 * i) * ldb);
        }
    };
    auto compute_stage = [&](int buf) {
        const uint32_t ab = a_off + buf * STAGE_T;
        const uint32_t bb = b_off + buf * STAGE_T;
#pragma unroll
        for (int kb = 0; kb < 2; kb++) {
            uint32_t afr[4][4], bfr[2][4];
#pragma unroll
            for (int mt = 0; mt < 4; mt++)
                LDSM_X4(afr[mt][0], afr[mt][1], afr[mt][2], afr[mt][3],
                        ab + mt * (16 * RPAD_B) + kb * 32);
#pragma unroll
            for (int t = 0; t < 2; t++)
                LDSM_X4(bfr[t][0], bfr[t][1], bfr[t][2], bfr[t][3],
                        bb + t * (16 * RPAD_B) + kb * 32);
#pragma unroll
            for (int mt = 0; mt < 4; mt++)
#pragma unroll
                for (int nt = 0; nt < 4; nt++)
                    mma_bf16(acc[mt][nt], afr[mt],
                             bfr[nt >> 1][nt & 1], bfr[nt >> 1][2 + (nt & 1)]);
        }
    };

    const int nst = K >> 5;                         // >= 16 for all our shapes
#pragma unroll
    for (int s = 0; s < NSTAGE - 1; s++) { issue_stage(s); CP_COMMIT(); }
    for (int s = 0; s < nst; s++) {
        CP_WAIT(NSTAGE - 2);
        __syncthreads();
        if (s + NSTAGE - 1 < nst) issue_stage(s + NSTAGE - 1);
        CP_COMMIT();
        compute_stage(s & (NSTAGE - 1));
    }

    // ---- epilogue
    float* Cf = (float*)Cv;
    __nv_bfloat16* Cb = (__nv_bfloat16*)Cv;
    const int lr  = l >> 2;
    const int lc2 = (l & 3) * 2;
#pragma unroll
    for (int mt = 0; mt < 4; mt++) {
        const int rA = wm * 64 + mt * 16 + lr;
        float blo = 0.f, bhi = 0.f;
        if (BIASMODE == 2) { blo = bias[row0 + rA]; bhi = bias[row0 + rA + 8]; }
#pragma unroll
        for (int nt = 0; nt < 4; nt++) {
            const int cA = wn * 32 + nt * 8 + lc2;
            float2 v0, v1;
            v0.x = acc[mt][nt][0] * alpha; v0.y = acc[mt][nt][1] * alpha;
            v1.x = acc[mt][nt][2] * alpha; v1.y = acc[mt][nt][3] * alpha;
            if (BIASMODE == 1) {
                float2 bb2 = *(const float2*)(bias + col0 + cA);
                v0.x += bb2.x; v0.y += bb2.y; v1.x += bb2.x; v1.y += bb2.y;
            } else if (BIASMODE == 2) {
                v0.x += blo; v0.y += blo; v1.x += bhi; v1.y += bhi;
            }
            if (RES) {
                float2 q0 = *(const float2*)(Rp + (long long)rA * ldc + cA);
                float2 q1 = *(const float2*)(Rp + (long long)(rA + 8) * ldc + cA);
                v0.x += q0.x; v0.y += q0.y; v1.x += q1.x; v1.y += q1.y;
            }
            if (OUTBF16) {
                *(__nv_bfloat162*)(Cb + cbase + (long long)rA * ldc + cA) =
                    __float22bfloat162_rn(v0);
                *(__nv_bfloat162*)(Cb + cbase + (long long)(rA + 8) * ldc + cA) =
                    __float22bfloat162_rn(v1);
            } else {
                *(float2*)(Cf + cbase + (long long)rA * ldc + cA) = v0;
                *(float2*)(Cf + cbase + (long long)(rA + 8) * ldc + cA) = v1;
            }
        }
    }
}

// ---------------- X -> bf16 ----------------
__global__ __launch_bounds__(256) void cvt_x_k(const float* __restrict__ X,
                                               __nv_bfloat16* __restrict__ Xb)
{
    const size_t i = ((size_t)blockIdx.x * 256 + threadIdx.x) * 4;
    float4 v = *(const float4*)(X + i);
    *(__nv_bfloat162*)(Xb + i)     = __float22bfloat162_rn(make_float2(v.x, v.y));
    *(__nv_bfloat162*)(Xb + i + 2) = __float22bfloat162_rn(make_float2(v.z, v.w));
}

// ---------------- weight transpose -> bf16: WT[n,k] = W[k,n] ----------------
__global__ __launch_bounds__(256) void transpose4_k(
    const float* __restrict__ w0, const float* __restrict__ w1,
    const float* __restrict__ w2, const float* __restrict__ w3,
    __nv_bfloat16* __restrict__ out)
{
    __shared__ float t[32][33];
    const int z = blockIdx.z;
    const float* W = (z == 0) ? w0 : (z == 1) ? w1 : (z == 2) ? w2 : w3;
    __nv_bfloat16* O = out + (size_t)z * Dq * Hq;
    const int tx = threadIdx.x & 31;
    const int ty = threadIdx.x >> 5;
    const int x = blockIdx.x * 32 + tx;
    const int y0 = blockIdx.y * 32;
#pragma unroll
    for (int i = ty; i < 32; i += 8) t[i][tx] = W[(y0 + i) * Hq + x];
    __syncthreads();
    const int ox = blockIdx.y * 32 + tx;
#pragma unroll
    for (int i = ty; i < 32; i += 8)
        O[(blockIdx.x * 32 + i) * Dq + ox] = __float2bfloat16_rn(t[tx][i]);
}

// ---------------- softmax in-place on bf16 rows of [16384][2048] ----------------
__global__ __launch_bounds__(256) void softmax_k(__nv_bfloat16* __restrict__ S)
{
    __shared__ float red[256];
    __nv_bfloat16* p = S + blockIdx.x * (long long)Nq;
    const int t = threadIdx.x;

    // each thread: 8 consecutive bf16 = one 16B chunk
    uint4 raw = *(const uint4*)(p + t * 8);
    const __nv_bfloat162* h2 = (const __nv_bfloat162*)&raw;
    float v[8];
#pragma unroll
    for (int i = 0; i < 4; i++) {
        float2 f = __bfloat1622float2(h2[i]);
        v[2 * i] = f.x; v[2 * i + 1] = f.y;
    }
    float mx = v[0];
#pragma unroll
    for (int i = 1; i < 8; i++) mx = fmaxf(mx, v[i]);
    red[t] = mx; __syncthreads();
    for (int s = 128; s > 0; s >>= 1) { if (t < s) red[t] = fmaxf(red[t], red[t + s]); __syncthreads(); }
    const float m = red[0]; __syncthreads();
    float sum = 0.f;
#pragma unroll
    for (int i = 0; i < 8; i++) { v[i] = __expf(v[i] - m); sum += v[i]; }
    red[t] = sum; __syncthreads();
    for (int s = 128; s > 0; s >>= 1) { if (t < s) red[t] += red[t + s]; __syncthreads(); }
    const float inv = 1.f / red[0];
    uint4 outw;
    __nv_bfloat162* o2 = (__nv_bfloat162*)&outw;
#pragma unroll
    for (int i = 0; i < 4; i++)
        o2[i] = __float22bfloat162_rn(make_float2(v[2 * i] * inv, v[2 * i + 1] * inv));
    *(uint4*)(p + t * 8) = outw;
}

// ---------------- LayerNorm over last dim (512) ----------------
__global__ __launch_bounds__(256) void ln_k(
    const float* __restrict__ in, const float* __restrict__ gamma,
    const float* __restrict__ beta, float* __restrict__ out)
{
    __shared__ float red[256];
    const float* p = in + blockIdx.x * (long long)Dq;
    const int t = threadIdx.x;
    float a = p[t], b = p[t + 256];
    red[t] = a + b; __syncthreads();
    for (int s = 128; s > 0; s >>= 1) { if (t < s) red[t] += red[t + s]; __syncthreads(); }
    const float mu = red[0] * (1.f / Dq); __syncthreads();
    float da = a - mu, db = b - mu;
    red[t] = da * da + db * db; __syncthreads();
    for (int s = 128; s > 0; s >>= 1) { if (t < s) red[t] += red[t + s]; __syncthreads(); }
    const float inv = rsqrtf(red[0] * (1.f / Dq) + 1e-5f);
    out[blockIdx.x * (long long)Dq + t]       = da * inv * gamma[t]       + beta[t];
    out[blockIdx.x * (long long)Dq + t + 256] = db * inv * gamma[t + 256] + beta[t + 256];
}

// ---------------- launch ----------------
extern "C" void kernel_launch(void* const* d_in, const int* in_sizes, int n_in,
                              void* d_out, int out_size)
{
    const float* X   = (const float*)d_in[0];
    const float* Wq  = (const float*)d_in[1];
    const float* bqp = (const float*)d_in[2];
    const float* Wk  = (const float*)d_in[3];
    const float* bkp = (const float*)d_in[4];
    const float* Wv  = (const float*)d_in[5];
    const float* bvp = (const float*)d_in[6];
    const float* Wo  = (const float*)d_in[7];
    const float* bop = (const float*)d_in[8];
    const float* ga  = (const float*)d_in[9];
    const float* be  = (const float*)d_in[10];
    float* out = (float*)d_out;

    void *pxb, *pqb, *pkb, *pvTb, *pctxb, *pattnb, *pwtb, *ptmp;
    cudaGetSymbolAddress(&pxb, g_xb);
    cudaGetSymbolAddress(&pqb, g_qb);
    cudaGetSymbolAddress(&pkb, g_kb);
    cudaGetSymbolAddress(&pvTb, g_vTb);
    cudaGetSymbolAddress(&pctxb, g_ctxb);
    cudaGetSymbolAddress(&pattnb, g_attnb);
    cudaGetSymbolAddress(&pwtb, g_wtb);
    cudaGetSymbolAddress(&ptmp, g_tmp);
    __nv_bfloat16* xb    = (__nv_bfloat16*)pxb;
    __nv_bfloat16* qb    = (__nv_bfloat16*)pqb;
    __nv_bfloat16* kb    = (__nv_bfloat16*)pkb;
    __nv_bfloat16* vTb   = (__nv_bfloat16*)pvTb;
    __nv_bfloat16* ctxb  = (__nv_bfloat16*)pctxb;
    __nv_bfloat16* attnb = (__nv_bfloat16*)pattnb;
    __nv_bfloat16* wtb   = (__nv_bfloat16*)pwtb;
    float* tmp = (float*)ptmp;
    __nv_bfloat16* WqT = wtb;
    __nv_bfloat16* WkT = wtb + (size_t)Dq * Hq;
    __nv_bfloat16* WvT = wtb + (size_t)2 * Dq * Hq;
    __nv_bfloat16* WoT = wtb + (size_t)3 * Dq * Hq;

    cudaFuncSetAttribute(mma_gemm<1, false, true>, cudaFuncAttributeMaxDynamicSharedMemorySize, SMEM_TOTAL);
    cudaFuncSetAttribute(mma_gemm<2, false, true>, cudaFuncAttributeMaxDynamicSharedMemorySize, SMEM_TOTAL);
    cudaFuncSetAttribute(mma_gemm<0, false, true>, cudaFuncAttributeMaxDynamicSharedMemorySize, SMEM_TOTAL);
    cudaFuncSetAttribute(mma_gemm<1, true, false>, cudaFuncAttributeMaxDynamicSharedMemorySize, SMEM_TOTAL);

    const float inv_sqrt_h = 0.04419417382415922f;  // 1/sqrt(512)
    dim3 blk(256);

    // 0. convert X; transpose+convert weights
    cvt_x_k<<<(ROWS * Dq) / (256 * 4), blk>>>(X, xb);
    transpose4_k<<<dim3(16, 16, 4), blk>>>(Wq, Wk, Wv, Wo, wtb);

    // 1. q = X @ Wq + bq  (bf16)
    mma_gemm<1, false, true><<<dim3(Hq / 128, ROWS / 128, 1), blk, SMEM_TOTAL>>>(
        xb, WqT, bqp, nullptr, qb, Dq, Dq, Dq, Hq, 0, 0, 0, 1.f);
    // 2. k = X @ Wk + bk  (bf16)
    mma_gemm<1, false, true><<<dim3(Hq / 128, ROWS / 128, 1), blk, SMEM_TOTAL>>>(
        xb, WkT, bkp, nullptr, kb, Dq, Dq, Dq, Hq, 0, 0, 0, 1.f);
    // 3. vT[h,n] = Wv[:,h].X[n,:] + bv[h]  (bf16, row bias)
    mma_gemm<2, false, true><<<dim3(ROWS / 128, Hq / 128, 1), blk, SMEM_TOTAL>>>(
        WvT, xb, bvp, nullptr, vTb, Dq, Dq, Dq, ROWS, 0, 0, 0, 1.f);
    // 4. scores = q @ k^T / sqrt(H)  (bf16 out, batched)
    mma_gemm<0, false, true><<<dim3(Nq / 128, Nq / 128, Bq), blk, SMEM_TOTAL>>>(
        qb, kb, nullptr, nullptr, attnb, Hq, Hq, Hq, Nq,
        (long long)Nq * Hq, (long long)Nq * Hq, (long long)Nq * Nq, inv_sqrt_h);
    // 5. softmax in place (bf16)
    softmax_k<<<ROWS, blk>>>(attnb);
    // 6. ctx = attn @ v  (bf16)
    mma_gemm<0, false, true><<<dim3(Hq / 128, Nq / 128, Bq), blk, SMEM_TOTAL>>>(
        attnb, vTb, nullptr, nullptr, ctxb, Nq, Nq, ROWS, Hq,
        (long long)Nq * Nq, (long long)Nq, (long long)Nq * Hq, 1.f);
    // 7. out_pre = ctx @ Wo + bo + X  (fp32)
    mma_gemm<1, true, false><<<dim3(Dq / 128, ROWS / 128, 1), blk, SMEM_TOTAL>>>(
        ctxb, WoT, bop, X, tmp, Hq, Hq, Hq, Dq, 0, 0, 0, 1.f);
    // 8. LayerNorm
    ln_k<<<ROWS, blk>>>(tmp, ga, be, out);
}